// round 16
// baseline (speedup 1.0000x reference)
#include <cuda_runtime.h>
#include <cuda_bf16.h>
#include <cstdint>
#include <cstddef>

#define B_ 32
#define T_ 64
#define S_ 64
#define H_ 256
#define V_ 32000

// ---------------- device scratch (no runtime allocations allowed) ----------------
__device__ __align__(16) float g_annproj[B_ * S_ * H_];      // ann @ W1[H:] + b1
__device__ __align__(16) float g_xWi[B_ * T_ * 3 * H_];      // emb[tok] @ Wi*[H:] + bi*
__device__ __align__(16) float g_hidden[B_ * T_ * H_];       // scan outputs, tf32-rounded
__device__ __align__(16) float g_wout[(size_t)H_ * V_];      // Wout, tf32-rounded

__device__ __forceinline__ float f2tf_val(float x) {
    unsigned r;
    asm("cvt.rna.tf32.f32 %0, %1;" : "=r"(r) : "f"(x));
    return __uint_as_float(r);
}

// =========================================================================
// Kernel 1: precompute annproj and xWi.  16 output rows per block.
// grid.x = 512: kind = bid>>7 (0=ann,1=z,2=r,3=h), tile = bid&127.
// =========================================================================
__global__ __launch_bounds__(256) void prep_kernel(
    const int* __restrict__ inputs, const float* __restrict__ ann,
    const float* __restrict__ emb,
    const float* __restrict__ W1,  const float* __restrict__ b1,
    const float* __restrict__ Wiz, const float* __restrict__ biz,
    const float* __restrict__ Wir, const float* __restrict__ bir,
    const float* __restrict__ Wih, const float* __restrict__ bih)
{
    __shared__ float a_s[16][H_];
    __shared__ int s_tok[16];
    const int tid  = threadIdx.x;
    const int kind = blockIdx.x >> 7;
    const int r0   = (blockIdx.x & 127) * 16;

    if (kind != 0 && tid < 16) s_tok[tid] = inputs[r0 + tid];
    __syncthreads();

    #pragma unroll
    for (int it = 0; it < 4; it++) {
        int id = tid + it * 256;
        int r  = id >> 6;
        int q  = id & 63;
        const float* src = (kind == 0)
            ? ann + (size_t)(r0 + r) * H_
            : emb + (size_t)s_tok[r] * H_;
        ((float4*)&a_s[r][0])[q] = ((const float4*)src)[q];
    }
    __syncthreads();

    const float* W; const float* bias;
    if (kind == 0)      { W = W1  + H_ * H_; bias = b1;  }
    else if (kind == 1) { W = Wiz + H_ * H_; bias = biz; }
    else if (kind == 2) { W = Wir + H_ * H_; bias = bir; }
    else                { W = Wih + H_ * H_; bias = bih; }

    const int j = tid;
    float acc[16];
    const float bj = bias[j];
    #pragma unroll
    for (int r = 0; r < 16; r++) acc[r] = bj;

    const float* Wj = W + j;
    #pragma unroll 2
    for (int k4 = 0; k4 < H_ / 4; k4++) {
        float w0 = Wj[(size_t)(4 * k4 + 0) * H_];
        float w1 = Wj[(size_t)(4 * k4 + 1) * H_];
        float w2 = Wj[(size_t)(4 * k4 + 2) * H_];
        float w3 = Wj[(size_t)(4 * k4 + 3) * H_];
        #pragma unroll
        for (int r = 0; r < 16; r++) {
            float4 a4 = *(const float4*)&a_s[r][k4 * 4];
            acc[r] = fmaf(a4.x, w0, acc[r]);
            acc[r] = fmaf(a4.y, w1, acc[r]);
            acc[r] = fmaf(a4.z, w2, acc[r]);
            acc[r] = fmaf(a4.w, w3, acc[r]);
        }
    }

    if (kind == 0) {
        #pragma unroll
        for (int r = 0; r < 16; r++)
            g_annproj[(size_t)(r0 + r) * H_ + j] = acc[r];
    } else {
        const int g = kind - 1;
        #pragma unroll
        for (int r = 0; r < 16; r++)
            g_xWi[((size_t)(r0 + r) * 3 + g) * H_ + j] = acc[r];
    }
}

// =========================================================================
// Kernel 1b: round Wout to tf32 once.
// =========================================================================
__global__ __launch_bounds__(256) void wout_cvt_kernel(const float* __restrict__ Wout)
{
    size_t idx = ((size_t)blockIdx.x * 256 + threadIdx.x) * 4;
    float4 v = *(const float4*)(Wout + idx);
    v.x = f2tf_val(v.x); v.y = f2tf_val(v.y);
    v.z = f2tf_val(v.z); v.w = f2tf_val(v.w);
    *(float4*)(g_wout + idx) = v;
}

// =========================================================================
// Kernel 2: cluster-quad scan, 2 BATCHES PER CLUSTER. Grid 64, cluster(4,1,1).
// Cluster cl serves batches {2cl, 2cl+1}; rank r owns weight columns
// [64r, 64r+64). Each weight load is FMA'd against both batches (2x reuse).
// 512 threads/CTA; cross-CTA state via st.shared::cluster + barrier.cluster.
// SMEM float offsets (per CTA):
// =========================================================================
#define Y_ANN  0        /* 8192: ann[2][64][own 64 j]     */
#define Y_AP   8192     /* 8192: annproj                  */
#define Y_H    16384    /* 512 : h[2][256] (peers fill)   */
#define Y_Q    16896    /* 128 : q[2][own 64]             */
#define Y_HW   17024    /* 384 : hw[3][2][64]             */
#define Y_CI   17408    /* 384 : ci[3][2][64]             */
#define Y_CTX  17792    /* 512 : ctx[2][256]              */
#define Y_W2   18304    /* 64  : W2 own columns           */
#define Y_U    18368    /* 512 : u[2][4 ranks][64]        */
#define Y_AW   18880    /* 128 : aw[2][64]                */
#define Y_RED  19008    /* 16                              */
#define Y_BIAS 19024    /* 192 : bh[3][64] own columns    */
#define Y_P1   19216    /* 1536: [4*32*3][2 batch][2 col] */
#define Y_P5   20752    /* 1152                            */
#define Y_TOT  21904
#define QSCAN_SMEM_BYTES (Y_TOT * 4)

__device__ __forceinline__ void st_peer(uint32_t pbase, int foff, float v) {
    asm volatile("st.shared::cluster.f32 [%0], %1;"
                 :: "r"(pbase + 4u * (uint32_t)foff), "f"(v) : "memory");
}

__device__ __forceinline__ void cluster_sync_all() {
    __syncthreads();
    asm volatile("barrier.cluster.arrive.aligned;" ::: "memory");
    asm volatile("barrier.cluster.wait.aligned;" ::: "memory");
}

__global__ void __cluster_dims__(4, 1, 1) __launch_bounds__(512, 1) scan_kernel(
    const float* __restrict__ ann,  const float* __restrict__ hinit,
    const float* __restrict__ W1,   const float* __restrict__ W2v,
    const float* __restrict__ b2,
    const float* __restrict__ Wiz,  const float* __restrict__ Wir,
    const float* __restrict__ Wih,
    const float* __restrict__ Whz,  const float* __restrict__ bhz,
    const float* __restrict__ Whr,  const float* __restrict__ bhr,
    const float* __restrict__ Whh,  const float* __restrict__ bhh,
    float* __restrict__ attn_out)
{
    extern __shared__ float sm[];

    const int cid  = blockIdx.x;
    const int b0   = (cid >> 2) * 2;    // first batch of this cluster
    const int rank = cid & 3;
    const int j0   = rank * 64;
    const int tid  = threadIdx.x;

    uint32_t sbase = (uint32_t)__cvta_generic_to_shared(sm);
    uint32_t pb[3];
    {
        int pi = 0;
        #pragma unroll
        for (int r = 0; r < 4; r++) {
            if (r != rank) {
                uint32_t a;
                asm("mapa.shared::cluster.u32 %0, %1, %2;"
                    : "=r"(a) : "r"(sbase), "r"(r));
                pb[pi++] = a;
            }
        }
    }

    // ---- one-time init ----
    #pragma unroll
    for (int i = 0; i < 4; i++) {
        int idx = tid + i * 512;            // 0..2047 float4 slots
        int bb  = idx >> 10;
        int row = (idx >> 4) & 63, q = idx & 15;
        ((float4*)(sm + Y_ANN))[idx] =
            *(const float4*)(ann + (size_t)(b0 + bb) * S_ * H_ + (size_t)row * H_ + j0 + 4 * q);
        ((float4*)(sm + Y_AP))[idx] =
            *(const float4*)(g_annproj + (size_t)(b0 + bb) * S_ * H_ + (size_t)row * H_ + j0 + 4 * q);
    }
    {
        int bb = tid >> 8, j = tid & 255;
        sm[Y_H + bb * 256 + j] = hinit[(size_t)(b0 + bb) * H_ + j];
    }
    if (tid < 64)  sm[Y_W2 + tid] = W2v[j0 + tid];
    if (tid < 192) {
        int m = tid >> 6, jj = tid & 63;
        const float* bp = (m == 0 ? bhz : m == 1 ? bhr : bhh);
        sm[Y_BIAS + tid] = bp[j0 + jj];
    }
    const float b2v = b2[0];

    // ---- per-thread roles (weight loops) ----
    const int m1 = tid >> 7;            // 0..3 stage1 matrix; 0..2 valid stage5
    const int kq = (tid >> 5) & 3;      // k-quarter
    const int cp = tid & 31;            // column pair (2 cols of own 64)
    const float* Ws1 = (m1 == 0 ? W1 : m1 == 1 ? Whz : m1 == 2 ? Whr : Whh);
    const float* Ws5 = (m1 == 0 ? Wiz : m1 == 1 ? Wir : Wih);
    const float2* wb1 = (const float2*)(Ws1 + (size_t)(kq * 64) * H_ + j0 + 2 * cp);
    const float2* wb5 = (const float2*)(Ws5 + (size_t)(kq * 64) * H_ + j0 + 2 * cp);

    cluster_sync_all();

    for (int t = 0; t < T_; t++) {
        // ========== stage 1: q / hw own columns, both batches ==========
        {
            float a0x0 = 0.f, a0y0 = 0.f, a0x1 = 0.f, a0y1 = 0.f;   // batch 0
            float a1x0 = 0.f, a1y0 = 0.f, a1x1 = 0.f, a1y1 = 0.f;   // batch 1
            const float4* hp0 = (const float4*)(sm + Y_H) + kq * 16;
            const float4* hp1 = (const float4*)(sm + Y_H + 256) + kq * 16;
            #pragma unroll 4
            for (int k4 = 0; k4 < 16; k4++) {
                float4 h0 = hp0[k4];
                float4 h1 = hp1[k4];
                float2 w0 = wb1[(4 * k4 + 0) * 128];
                float2 w1 = wb1[(4 * k4 + 1) * 128];
                float2 w2 = wb1[(4 * k4 + 2) * 128];
                float2 w3 = wb1[(4 * k4 + 3) * 128];
                a0x0 = fmaf(h0.x, w0.x, a0x0); a0y0 = fmaf(h0.x, w0.y, a0y0);
                a0x1 = fmaf(h0.y, w1.x, a0x1); a0y1 = fmaf(h0.y, w1.y, a0y1);
                a0x0 = fmaf(h0.z, w2.x, a0x0); a0y0 = fmaf(h0.z, w2.y, a0y0);
                a0x1 = fmaf(h0.w, w3.x, a0x1); a0y1 = fmaf(h0.w, w3.y, a0y1);
                a1x0 = fmaf(h1.x, w0.x, a1x0); a1y0 = fmaf(h1.x, w0.y, a1y0);
                a1x1 = fmaf(h1.y, w1.x, a1x1); a1y1 = fmaf(h1.y, w1.y, a1y1);
                a1x0 = fmaf(h1.z, w2.x, a1x0); a1y0 = fmaf(h1.z, w2.y, a1y0);
                a1x1 = fmaf(h1.w, w3.x, a1x1); a1y1 = fmaf(h1.w, w3.y, a1y1);
            }
            float s0x = a0x0 + a0x1, s0y = a0y0 + a0y1;
            float s1x = a1x0 + a1x1, s1y = a1y0 + a1y1;
            if (kq != 0) {
                int base = Y_P1 + ((m1 * 32 + cp) * 3 + (kq - 1)) * 4;
                sm[base]     = s0x; sm[base + 1] = s0y;
                sm[base + 2] = s1x; sm[base + 3] = s1y;
            }
            __syncthreads();
            if (kq == 0) {
                int base = Y_P1 + (m1 * 32 + cp) * 12;
                float o0x = s0x + sm[base]     + sm[base + 4] + sm[base + 8];
                float o0y = s0y + sm[base + 1] + sm[base + 5] + sm[base + 9];
                float o1x = s1x + sm[base + 2] + sm[base + 6] + sm[base + 10];
                float o1y = s1y + sm[base + 3] + sm[base + 7] + sm[base + 11];
                if (m1 == 0) {
                    sm[Y_Q + 2 * cp]          = o0x;
                    sm[Y_Q + 2 * cp + 1]      = o0y;
                    sm[Y_Q + 64 + 2 * cp]     = o1x;
                    sm[Y_Q + 64 + 2 * cp + 1] = o1y;
                } else {
                    float bz0 = sm[Y_BIAS + (m1 - 1) * 64 + 2 * cp];
                    float bz1 = sm[Y_BIAS + (m1 - 1) * 64 + 2 * cp + 1];
                    int hb = Y_HW + (m1 - 1) * 128;
                    sm[hb + 2 * cp]          = o0x + bz0;
                    sm[hb + 2 * cp + 1]      = o0y + bz1;
                    sm[hb + 64 + 2 * cp]     = o1x + bz0;
                    sm[hb + 64 + 2 * cp + 1] = o1y + bz1;
                }
            }
        }
        __syncthreads();

        // ========== stage 2: partial scores, both batches ==========
        {
            const int bb = tid >> 8;
            const int s  = (tid >> 2) & 63;
            const int p  = tid & 3;
            float part = 0.f;
            #pragma unroll
            for (int i = 0; i < 16; i++) {
                int jj = p + 4 * ((i + s) & 15);   // conflict-free rotation
                float v = fmaxf(sm[Y_Q + bb * 64 + jj] + sm[Y_AP + bb * 4096 + s * 64 + jj], 0.f);
                part = fmaf(v, sm[Y_W2 + jj], part);
            }
            part += __shfl_xor_sync(0xffffffffu, part, 1);
            part += __shfl_xor_sync(0xffffffffu, part, 2);
            if (p == 0) {
                int off = Y_U + bb * 256 + rank * 64 + s;
                sm[off] = part;
                st_peer(pb[0], off, part);
                st_peer(pb[1], off, part);
                st_peer(pb[2], off, part);
            }
        }
        cluster_sync_all();   // #1: score partials exchanged

        // ========== stage 3: softmax, both batches (all ranks) ==========
        {
            float uv = -1e30f;
            const int bb = tid >> 6, s = tid & 63, w = tid >> 5;
            if (tid < 128) {
                int base = Y_U + bb * 256;
                uv = sm[base + s] + sm[base + 64 + s]
                   + sm[base + 128 + s] + sm[base + 192 + s] + b2v;
                float m = uv;
                #pragma unroll
                for (int o = 16; o > 0; o >>= 1)
                    m = fmaxf(m, __shfl_xor_sync(0xffffffffu, m, o));
                if ((tid & 31) == 0) sm[Y_RED + w] = m;
            }
            __syncthreads();
            float ev = 0.f;
            if (tid < 128) {
                float gmax = fmaxf(sm[Y_RED + 2 * bb], sm[Y_RED + 2 * bb + 1]);
                ev = __expf(uv - gmax);
                float ssum = ev;
                #pragma unroll
                for (int o = 16; o > 0; o >>= 1)
                    ssum += __shfl_xor_sync(0xffffffffu, ssum, o);
                if ((tid & 31) == 0) sm[Y_RED + 8 + w] = ssum;
            }
            __syncthreads();
            if (tid < 128) {
                float aw = ev / (sm[Y_RED + 8 + 2 * bb] + sm[Y_RED + 8 + 2 * bb + 1]);
                sm[Y_AW + tid] = aw;
                if (rank == 0)
                    attn_out[(size_t)(b0 + bb) * S_ * T_ + (size_t)s * T_ + t] = aw;
            }
        }
        __syncthreads();

        // ========== stage 4: context own columns + xWi prefetch ==========
        float xz = 0.f, xr = 0.f, xh = 0.f;
        if (tid < 128) {
            const int bb = tid >> 6, j = tid & 63;
            const size_t xo = ((size_t)((b0 + bb) * T_ + t) * 3) * H_ + j0 + j;
            xz = g_xWi[xo]; xr = g_xWi[xo + H_]; xh = g_xWi[xo + 2 * H_];
            float ctx = 0.f;
            #pragma unroll
            for (int s2 = 0; s2 < 64; s2++)
                ctx = fmaf(sm[Y_AW + bb * 64 + s2], sm[Y_ANN + bb * 4096 + s2 * 64 + j], ctx);
            int off = Y_CTX + bb * 256 + j0 + j;
            sm[off] = ctx;
            st_peer(pb[0], off, ctx);
            st_peer(pb[1], off, ctx);
            st_peer(pb[2], off, ctx);
        }
        cluster_sync_all();   // #2: full ctx (both batches) on all ranks

        // ========== stage 5: ci = ctx @ Wi*[:H] own columns, both batches ==
        {
            float a0x0 = 0.f, a0y0 = 0.f, a0x1 = 0.f, a0y1 = 0.f;
            float a1x0 = 0.f, a1y0 = 0.f, a1x1 = 0.f, a1y1 = 0.f;
            if (m1 < 3) {
                const float4* c0 = (const float4*)(sm + Y_CTX) + kq * 16;
                const float4* c1 = (const float4*)(sm + Y_CTX + 256) + kq * 16;
                #pragma unroll 4
                for (int k4 = 0; k4 < 16; k4++) {
                    float4 h0 = c0[k4];
                    float4 h1 = c1[k4];
                    float2 w0 = wb5[(4 * k4 + 0) * 128];
                    float2 w1 = wb5[(4 * k4 + 1) * 128];
                    float2 w2 = wb5[(4 * k4 + 2) * 128];
                    float2 w3 = wb5[(4 * k4 + 3) * 128];
                    a0x0 = fmaf(h0.x, w0.x, a0x0); a0y0 = fmaf(h0.x, w0.y, a0y0);
                    a0x1 = fmaf(h0.y, w1.x, a0x1); a0y1 = fmaf(h0.y, w1.y, a0y1);
                    a0x0 = fmaf(h0.z, w2.x, a0x0); a0y0 = fmaf(h0.z, w2.y, a0y0);
                    a0x1 = fmaf(h0.w, w3.x, a0x1); a0y1 = fmaf(h0.w, w3.y, a0y1);
                    a1x0 = fmaf(h1.x, w0.x, a1x0); a1y0 = fmaf(h1.x, w0.y, a1y0);
                    a1x1 = fmaf(h1.y, w1.x, a1x1); a1y1 = fmaf(h1.y, w1.y, a1y1);
                    a1x0 = fmaf(h1.z, w2.x, a1x0); a1y0 = fmaf(h1.z, w2.y, a1y0);
                    a1x1 = fmaf(h1.w, w3.x, a1x1); a1y1 = fmaf(h1.w, w3.y, a1y1);
                }
            }
            float s0x = a0x0 + a0x1, s0y = a0y0 + a0y1;
            float s1x = a1x0 + a1x1, s1y = a1y0 + a1y1;
            if (m1 < 3 && kq != 0) {
                int base = Y_P5 + ((m1 * 32 + cp) * 3 + (kq - 1)) * 4;
                sm[base]     = s0x; sm[base + 1] = s0y;
                sm[base + 2] = s1x; sm[base + 3] = s1y;
            }
            __syncthreads();
            if (m1 < 3 && kq == 0) {
                int base = Y_P5 + (m1 * 32 + cp) * 12;
                int cb = Y_CI + m1 * 128;
                sm[cb + 2 * cp] =
                    s0x + sm[base] + sm[base + 4] + sm[base + 8];
                sm[cb + 2 * cp + 1] =
                    s0y + sm[base + 1] + sm[base + 5] + sm[base + 9];
                sm[cb + 64 + 2 * cp] =
                    s1x + sm[base + 2] + sm[base + 6] + sm[base + 10];
                sm[cb + 64 + 2 * cp + 1] =
                    s1y + sm[base + 3] + sm[base + 7] + sm[base + 11];
            }
        }
        __syncthreads();

        // ========== stage 6: GRU gates, both batches ==========
        if (tid < 128) {
            const int bb = tid >> 6, j = tid & 63;
            float hprev = sm[Y_H + bb * 256 + j0 + j];
            float z = 1.f / (1.f + __expf(-(sm[Y_CI + bb * 64 + j]       + xz + sm[Y_HW + bb * 64 + j])));
            float r = 1.f / (1.f + __expf(-(sm[Y_CI + 128 + bb * 64 + j] + xr + sm[Y_HW + 128 + bb * 64 + j])));
            float g = tanhf(sm[Y_CI + 256 + bb * 64 + j] + xh + r * sm[Y_HW + 256 + bb * 64 + j]);
            float hn = (1.f - z) * g + z * hprev;
            int off = Y_H + bb * 256 + j0 + j;
            sm[off] = hn;
            st_peer(pb[0], off, hn);
            st_peer(pb[1], off, hn);
            st_peer(pb[2], off, hn);
            g_hidden[(size_t)((b0 + bb) * T_ + t) * H_ + j0 + j] = f2tf_val(hn);
        }
        cluster_sync_all();   // #3: full h_new (both batches) on all ranks
    }
}

// =========================================================================
// Kernel 3: out[B*T, V] = hiddens @ Wout + bout (pre-rounded tf32 operands)
// tf32 mma m16n8k8, CTA tile 128x64, cp.async double-buffered.
// =========================================================================
#define GBM 128
#define GBN 64
#define GBK 32
#define AS_STRIDE 36
#define BS_STRIDE 72
#define GEMM_SMEM_FLOATS (2 * GBM * AS_STRIDE + 2 * GBK * BS_STRIDE)
#define GEMM_SMEM_BYTES  (GEMM_SMEM_FLOATS * 4)

__device__ __forceinline__ void cpasync16(void* smem_dst, const void* gsrc) {
    unsigned s = (unsigned)__cvta_generic_to_shared(smem_dst);
    asm volatile("cp.async.ca.shared.global [%0], [%1], 16;" :: "r"(s), "l"(gsrc));
}

__global__ __launch_bounds__(256) void out_gemm_kernel(
    const float* __restrict__ bout, float* __restrict__ out)
{
    extern __shared__ float gsm[];
    float* As = gsm;
    float* Bs = gsm + 2 * GBM * AS_STRIDE;

    const int tid  = threadIdx.x;
    const int wid  = tid >> 5;
    const int lane = tid & 31;
    const int g    = lane >> 2;
    const int tq   = lane & 3;
    const int wm   = wid & 3;
    const int wn   = wid >> 2;
    const int m0   = blockIdx.x * GBM;
    const int n0   = blockIdx.y * GBN;

    float c[2][4][4];
    #pragma unroll
    for (int a = 0; a < 2; a++)
        #pragma unroll
        for (int bb = 0; bb < 4; bb++)
            #pragma unroll
            for (int cc = 0; cc < 4; cc++) c[a][bb][cc] = 0.f;

    auto issue = [&](int kc_i) {
        const int kc = kc_i * GBK;
        float* Ab = As + (kc_i & 1) * GBM * AS_STRIDE;
        float* Bb = Bs + (kc_i & 1) * GBK * BS_STRIDE;
        #pragma unroll
        for (int it = 0; it < 4; it++) {
            int id = tid + it * 256;
            int m  = id >> 3;
            int q  = id & 7;
            cpasync16(&Ab[m * AS_STRIDE + q * 4],
                      &g_hidden[(size_t)(m0 + m) * H_ + kc + q * 4]);
        }
        #pragma unroll
        for (int it = 0; it < 2; it++) {
            int id = tid + it * 256;
            int k  = id >> 4;
            int nq = id & 15;
            cpasync16(&Bb[k * BS_STRIDE + nq * 4],
                      &g_wout[(size_t)(kc + k) * V_ + n0 + nq * 4]);
        }
        asm volatile("cp.async.commit_group;");
    };

    issue(0);

    for (int kc_i = 0; kc_i < H_ / GBK; kc_i++) {
        if (kc_i + 1 < H_ / GBK) {
            issue(kc_i + 1);
            asm volatile("cp.async.wait_group 1;");
        } else {
            asm volatile("cp.async.wait_group 0;");
        }
        __syncthreads();

        const float* Ab = As + (kc_i & 1) * GBM * AS_STRIDE;
        const float* Bb = Bs + (kc_i & 1) * GBK * BS_STRIDE;

        #pragma unroll
        for (int ks = 0; ks < 4; ks++) {
            const int K0 = ks * 8;
            unsigned af[2][4];
            #pragma unroll
            for (int mt = 0; mt < 2; mt++) {
                int row = wm * 32 + mt * 16 + g;
                af[mt][0] = __float_as_uint(Ab[(row    ) * AS_STRIDE + K0 + tq    ]);
                af[mt][1] = __float_as_uint(Ab[(row + 8) * AS_STRIDE + K0 + tq    ]);
                af[mt][2] = __float_as_uint(Ab[(row    ) * AS_STRIDE + K0 + tq + 4]);
                af[mt][3] = __float_as_uint(Ab[(row + 8) * AS_STRIDE + K0 + tq + 4]);
            }
            unsigned bf[4][2];
            #pragma unroll
            for (int nt = 0; nt < 4; nt++) {
                int col = wn * 32 + nt * 8 + g;
                bf[nt][0] = __float_as_uint(Bb[(K0 + tq    ) * BS_STRIDE + col]);
                bf[nt][1] = __float_as_uint(Bb[(K0 + tq + 4) * BS_STRIDE + col]);
            }
            #pragma unroll
            for (int mt = 0; mt < 2; mt++)
                #pragma unroll
                for (int nt = 0; nt < 4; nt++) {
                    asm volatile(
                        "mma.sync.aligned.m16n8k8.row.col.f32.tf32.tf32.f32 "
                        "{%0,%1,%2,%3}, {%4,%5,%6,%7}, {%8,%9}, {%0,%1,%2,%3};"
                        : "+f"(c[mt][nt][0]), "+f"(c[mt][nt][1]),
                          "+f"(c[mt][nt][2]), "+f"(c[mt][nt][3])
                        : "r"(af[mt][0]), "r"(af[mt][1]),
                          "r"(af[mt][2]), "r"(af[mt][3]),
                          "r"(bf[nt][0]), "r"(bf[nt][1]));
                }
        }
        __syncthreads();
    }

    #pragma unroll
    for (int mt = 0; mt < 2; mt++) {
        #pragma unroll
        for (int nt = 0; nt < 4; nt++) {
            int row = m0 + wm * 32 + mt * 16 + g;
            int col = n0 + wn * 32 + nt * 8 + 2 * tq;
            float bo0 = bout[col], bo1 = bout[col + 1];
            float2 v0 = make_float2(c[mt][nt][0] + bo0, c[mt][nt][1] + bo1);
            float2 v1 = make_float2(c[mt][nt][2] + bo0, c[mt][nt][3] + bo1);
            *(float2*)&out[(size_t)row * V_ + col]       = v0;
            *(float2*)&out[(size_t)(row + 8) * V_ + col] = v1;
        }
    }
}

// =========================================================================
extern "C" void kernel_launch(void* const* d_in, const int* in_sizes, int n_in,
                              void* d_out, int out_size)
{
    const int*   inputs = (const int*)  d_in[0];
    const float* ann    = (const float*)d_in[1];
    const float* hinit  = (const float*)d_in[2];
    const float* emb    = (const float*)d_in[3];
    const float* W1     = (const float*)d_in[4];
    const float* b1     = (const float*)d_in[5];
    const float* W2v    = (const float*)d_in[6];
    const float* b2     = (const float*)d_in[7];
    const float* Wiz    = (const float*)d_in[8];
    const float* biz    = (const float*)d_in[9];
    const float* Wir    = (const float*)d_in[10];
    const float* bir    = (const float*)d_in[11];
    const float* Wih    = (const float*)d_in[12];
    const float* bih    = (const float*)d_in[13];
    const float* Whz    = (const float*)d_in[14];
    const float* bhz    = (const float*)d_in[15];
    const float* Whr    = (const float*)d_in[16];
    const float* bhr    = (const float*)d_in[17];
    const float* Whh    = (const float*)d_in[18];
    const float* bhh    = (const float*)d_in[19];
    const float* Wout   = (const float*)d_in[20];
    const float* bout   = (const float*)d_in[21];

    float* out  = (float*)d_out;
    float* attn = out + (size_t)B_ * T_ * V_;   // outputs: (B,T,V) then (B,S,T)

    cudaFuncSetAttribute(scan_kernel,
                         cudaFuncAttributeMaxDynamicSharedMemorySize,
                         QSCAN_SMEM_BYTES);
    cudaFuncSetAttribute(out_gemm_kernel,
                         cudaFuncAttributeMaxDynamicSharedMemorySize,
                         GEMM_SMEM_BYTES);

    prep_kernel<<<512, 256>>>(inputs, ann, emb, W1, b1,
                              Wiz, biz, Wir, bir, Wih, bih);
    wout_cvt_kernel<<<8000, 256>>>(Wout);
    scan_kernel<<<64, 512, QSCAN_SMEM_BYTES>>>(ann, hinit, W1, W2v, b2,
                                               Wiz, Wir, Wih,
                                               Whz, bhz, Whr, bhr, Whh, bhh,
                                               attn);
    out_gemm_kernel<<<dim3(16, 500), 256, GEMM_SMEM_BYTES>>>(bout, out);
}